// round 10
// baseline (speedup 1.0000x reference)
#include <cuda_runtime.h>
#include <cstdint>

// Problem constants
#define N_TOKENS 131072
#define E_DIM    128
#define KCB      1024
#define NQ       4

// Tiling
#define T_BLK    128
#define NTHREADS 512
#define CHUNK    128
#define NCHUNKS  (KCB / CHUNK)
#define NBLOCKS  (N_TOKENS / T_BLK)

// Smem pitches (in floats)
#define XS_PITCH 132
#define XQ_PITCH 129

// Output layout (float32): x_q [N,128] | mean_loss [1] | all_indices [N,4]
#define OUT_XQ_ELEMS   ((size_t)N_TOKENS * E_DIM)
#define OUT_LOSS_OFF   OUT_XQ_ELEMS
#define OUT_IDX_OFF    (OUT_XQ_ELEMS + 1)

// Smem layout (floats)
#define SM_XS_F    (E_DIM * XS_PITCH)
#define SM_XQ_F    (T_BLK * XQ_PITCH)
#define SM_CBS_F   (CHUNK * E_DIM)
#define SM_RR_F    (T_BLK)
#define SM_LOSS_F  (T_BLK)
#define SM_TOTAL_F (SM_XS_F + SM_XQ_F + SM_CBS_F + SM_RR_F + SM_LOSS_F)
#define SMEM_BYTES (SM_TOTAL_F * 4)

__device__ float g_cc[NQ * KCB];
__device__ float g_partials[NBLOCKS];

// NEON-style vectorized sum-of-squares emulation (XLA:CPU fast-math reduce):
// VF=4, IC=2 -> 8 strided fused-FMA accumulators; vadd lanes; faddp pairwise.
__device__ __forceinline__ float neon_sumsq(const float* v, int stride) {
    float a0=0.f,a1=0.f,a2=0.f,a3=0.f,b0=0.f,b1=0.f,b2=0.f,b3=0.f;
    #pragma unroll 4
    for (int k = 0; k < E_DIM; k += 8) {
        float v0=v[(k+0)*stride], v1=v[(k+1)*stride], v2=v[(k+2)*stride], v3=v[(k+3)*stride];
        float v4=v[(k+4)*stride], v5=v[(k+5)*stride], v6=v[(k+6)*stride], v7=v[(k+7)*stride];
        a0=__fmaf_rn(v0,v0,a0); a1=__fmaf_rn(v1,v1,a1);
        a2=__fmaf_rn(v2,v2,a2); a3=__fmaf_rn(v3,v3,a3);
        b0=__fmaf_rn(v4,v4,b0); b1=__fmaf_rn(v5,v5,b1);
        b2=__fmaf_rn(v6,v6,b2); b3=__fmaf_rn(v7,v7,b3);
    }
    float s0=__fadd_rn(a0,b0), s1=__fadd_rn(a1,b1);
    float s2=__fadd_rn(a2,b2), s3=__fadd_rn(a3,b3);
    return __fadd_rn(__fadd_rn(s0,s1), __fadd_rn(s2,s3));   // pairwise (faddp)
}

// --- ||c||^2 via the same NEON reduce emulation.
__global__ void prep_kernel(const float* __restrict__ cb) {
    int c = blockIdx.x * blockDim.x + threadIdx.x;
    if (c < NQ * KCB)
        g_cc[c] = neon_sumsq(cb + (size_t)c * E_DIM, 1);
}

__global__ void __launch_bounds__(NTHREADS, 1)
rvq_kernel(const float* __restrict__ x, const float* __restrict__ cb, float* __restrict__ out)
{
    extern __shared__ float sm[];
    float* xs      = sm;                                // residual, transposed: xs[k*XS_PITCH + t]
    float* xq      = xs + SM_XS_F;
    float* cbs     = xq + SM_XQ_F;                      // codebook chunk / reduction aliases
    float* rr      = cbs + SM_CBS_F;
    float* lossbuf = rr + SM_RR_F;

    float* red_d2 = cbs;                                // [t][16][2] distances
    int*   red_i2 = (int*)(cbs + 4096);                 // [t][16][2] indices

    const int tid = threadIdx.x;
    const int tr  = tid & 31;
    const int tc  = tid >> 5;
    const int t0  = blockIdx.x * T_BLK;

    // ---- Load x tile (transposed), zero xq/lossbuf.
    {
        const float4* x4 = (const float4*)(x + (size_t)t0 * E_DIM);
        #pragma unroll
        for (int r = 0; r < (T_BLK * (E_DIM / 4)) / NTHREADS; ++r) {
            int f  = tid + NTHREADS * r;
            int t  = f >> 5;
            int k4 = f & 31;
            float4 v = x4[t * 32 + k4];
            xs[(k4 * 4 + 0) * XS_PITCH + t] = v.x;
            xs[(k4 * 4 + 1) * XS_PITCH + t] = v.y;
            xs[(k4 * 4 + 2) * XS_PITCH + t] = v.z;
            xs[(k4 * 4 + 3) * XS_PITCH + t] = v.w;
        }
        for (int o = tid; o < SM_XQ_F; o += NTHREADS) xq[o] = 0.0f;
        if (tid < T_BLK) lossbuf[tid] = 0.0f;
    }

    for (int s = 0; s <= NQ; ++s) {
        __syncthreads();
        // ---- ||r||^2 via NEON reduce emulation (matches reference's vectorized sum).
        if (tid < T_BLK) {
            float a = neon_sumsq(xs + tid, XS_PITCH);
            rr[tid] = a;
            if (s > 0) lossbuf[tid] += a;
        }
        __syncthreads();
        if (s == NQ) break;

        // Per-thread best-2 (bulk FMA path is selection-only; refinement decides).
        float d0[4], d1[4];
        int   i0[4], i1[4];
        #pragma unroll
        for (int i = 0; i < 4; ++i) {
            d0[i] = __int_as_float(0x7f800000); i0[i] = 0x7fffffff;
            d1[i] = __int_as_float(0x7f800000); i1[i] = 0x7fffffff;
        }

        const float4* cbg4 = (const float4*)(cb + (size_t)s * KCB * E_DIM);

        for (int ch = 0; ch < NCHUNKS; ++ch) {
            __syncthreads();
            {
                float4* cbs4 = (float4*)cbs;
                #pragma unroll
                for (int r = 0; r < (CHUNK * (E_DIM / 4)) / NTHREADS; ++r) {
                    int f  = tid + NTHREADS * r;
                    int c  = f >> 5;
                    int k4 = f & 31;
                    cbs4[c * 32 + k4] = cbg4[(size_t)(ch * CHUNK + c) * 32 + k4];
                }
            }
            __syncthreads();

            float acc[4][8];
            #pragma unroll
            for (int i = 0; i < 4; ++i)
                #pragma unroll
                for (int j = 0; j < 8; ++j) acc[i][j] = 0.0f;

            for (int k4 = 0; k4 < 32; ++k4) {
                float4 b[8];
                #pragma unroll
                for (int j = 0; j < 8; ++j)
                    b[j] = *(const float4*)&cbs[(tc * 8 + j) * E_DIM + k4 * 4];
                #pragma unroll
                for (int m = 0; m < 4; ++m) {
                    const float4 av = *(const float4*)&xs[(k4 * 4 + m) * XS_PITCH + tr * 4];
                    #pragma unroll
                    for (int j = 0; j < 8; ++j) {
                        const float bv = (m == 0) ? b[j].x : (m == 1) ? b[j].y
                                       : (m == 2) ? b[j].z : b[j].w;
                        acc[0][j] = __fmaf_rn(av.x, bv, acc[0][j]);
                        acc[1][j] = __fmaf_rn(av.y, bv, acc[1][j]);
                        acc[2][j] = __fmaf_rn(av.z, bv, acc[2][j]);
                        acc[3][j] = __fmaf_rn(av.w, bv, acc[3][j]);
                    }
                }
            }

            // bulk d (selection only), per-thread top-2
            #pragma unroll
            for (int i = 0; i < 4; ++i) {
                float rrt = rr[tr * 4 + i];
                #pragma unroll
                for (int j = 0; j < 8; ++j) {
                    int   c = ch * CHUNK + tc * 8 + j;
                    float d = __fadd_rn(__fmaf_rn(-2.0f, acc[i][j], rrt), g_cc[s * KCB + c]);
                    bool b0 = (d < d0[i]) || (d == d0[i] && c < i0[i]);
                    bool b1 = (d < d1[i]) || (d == d1[i] && c < i1[i]);
                    if (b0)      { d1[i]=d0[i]; i1[i]=i0[i]; d0[i]=d; i0[i]=c; }
                    else if (b1) { d1[i]=d;     i1[i]=c; }
                }
            }
        }

        __syncthreads();
        #pragma unroll
        for (int i = 0; i < 4; ++i) {
            int t = tr * 4 + i;
            red_d2[(t * 16 + tc) * 2 + 0] = d0[i];
            red_d2[(t * 16 + tc) * 2 + 1] = d1[i];
            red_i2[(t * 16 + tc) * 2 + 0] = i0[i];
            red_i2[(t * 16 + tc) * 2 + 1] = i1[i];
        }
        __syncthreads();

        if (tid < T_BLK) {
            // ---- block top-4
            float td[4]; int ti[4];
            #pragma unroll
            for (int q = 0; q < 4; ++q) { td[q] = __int_as_float(0x7f800000); ti[q] = 0x7fffffff; }
            for (int g = 0; g < 32; ++g) {
                float d = red_d2[tid * 32 + g];
                int   c = red_i2[tid * 32 + g];
                #pragma unroll
                for (int q = 0; q < 4; ++q) {
                    bool better = (d < td[q]) || (d == td[q] && c < ti[q]);
                    if (better) { float dt = td[q]; int ct = ti[q]; td[q] = d; ti[q] = c; d = dt; c = ct; }
                }
            }

            // ---- refinement: reference arithmetic emulation:
            //   dot = SEQUENTIAL ascending fused-FMA (Eigen gebp per-output chain)
            //   d   = fl( fl(rr - fl(2*dot)) + cc ), argmin lowest-index tie-break
            const float rrt = rr[tid];
            float bestv = 0.0f; int besti = -1;
            for (int q = 0; q < 4; ++q) {
                int c = ti[q];
                if (c == 0x7fffffff) continue;
                const float* crow = cb + (size_t)(s * KCB + c) * E_DIM;
                float hs = 0.0f;
                #pragma unroll 8
                for (int k = 0; k < E_DIM; ++k)
                    hs = __fmaf_rn(xs[k * XS_PITCH + tid], crow[k], hs);
                float dem = __fadd_rn(__fsub_rn(rrt, __fmul_rn(2.0f, hs)), g_cc[s * KCB + c]);
                if (besti < 0 || dem < bestv || (dem == bestv && c < besti)) { bestv = dem; besti = c; }
            }

            out[OUT_IDX_OFF + (size_t)(t0 + tid) * NQ + s] = (float)besti;

            // ---- faithful straight-through update
            const float4* qrow = (const float4*)(cb + (size_t)(s * KCB + besti) * E_DIM);
            #pragma unroll 4
            for (int k4 = 0; k4 < 32; ++k4) {
                float4 q4 = qrow[k4];
                #pragma unroll
                for (int m = 0; m < 4; ++m) {
                    int   k = k4 * 4 + m;
                    float qv = (m == 0) ? q4.x : (m == 1) ? q4.y : (m == 2) ? q4.z : q4.w;
                    float r  = xs[k * XS_PITCH + tid];
                    float qt = __fadd_rn(r, __fsub_rn(qv, r));
                    xq[tid * XQ_PITCH + k] = __fadd_rn(xq[tid * XQ_PITCH + k], qt);
                    xs[k * XS_PITCH + tid] = __fsub_rn(r, qt);
                }
            }
        }
    }

    if (tid == 0) {
        float a = 0.0f;
        for (int t = 0; t < T_BLK; ++t) a += lossbuf[t];
        g_partials[blockIdx.x] = a;
    }

    {
        float* o = out + (size_t)t0 * E_DIM;
        for (int f = tid; f < T_BLK * E_DIM; f += NTHREADS)
            o[f] = xq[(f >> 7) * XQ_PITCH + (f & 127)];
    }
}

__global__ void finalize_kernel(float* __restrict__ out) {
    if (threadIdx.x == 0 && blockIdx.x == 0) {
        double a = 0.0;
        for (int i = 0; i < NBLOCKS; ++i) a += (double)g_partials[i];
        out[OUT_LOSS_OFF] = (float)(a * (0.25 / (4.0 * (double)N_TOKENS * (double)E_DIM)));
    }
}

extern "C" void kernel_launch(void* const* d_in, const int* in_sizes, int n_in,
                              void* d_out, int out_size) {
    (void)in_sizes; (void)n_in; (void)out_size;
    const float* x  = (const float*)d_in[0];
    const float* cb = (const float*)d_in[1];
    float* out = (float*)d_out;

    cudaFuncSetAttribute(rvq_kernel, cudaFuncAttributeMaxDynamicSharedMemorySize, SMEM_BYTES);

    prep_kernel<<<(NQ * KCB + 255) / 256, 256>>>(cb);
    rvq_kernel<<<NBLOCKS, NTHREADS, SMEM_BYTES>>>(x, cb, out);
    finalize_kernel<<<1, 1>>>(out);
}

// round 11
// speedup vs baseline: 1.5914x; 1.5914x over previous
#include <cuda_runtime.h>
#include <cuda_bf16.h>
#include <cstdint>

// Problem constants
#define N_TOKENS 131072
#define E_DIM    128
#define KCB      1024
#define NQ       4

// Tiling
#define T_BLK    128
#define NTHREADS 512
#define CHUNK    128
#define NCHUNKS  (KCB / CHUNK)
#define NBLOCKS  (N_TOKENS / T_BLK)

// Pitches
#define XS_PITCH 129                 // fp32 residual, transposed [k][t]
#define XQ_PITCH 129                 // fp32 x_q accumulator [t][k]
#define BF_PITCH 136                 // bf16 rows: 272B = 16B-aligned, bank-rotating

// Output layout (float32): x_q [N,128] | mean_loss [1] | all_indices [N,4]
#define OUT_XQ_ELEMS   ((size_t)N_TOKENS * E_DIM)
#define OUT_LOSS_OFF   OUT_XQ_ELEMS
#define OUT_IDX_OFF    (OUT_XQ_ELEMS + 1)

// Smem layout (float indices)
#define OFF_XS   0
#define OFF_XQ   (OFF_XS + E_DIM * XS_PITCH)        // 16512
#define OFF_RR   (OFF_XQ + T_BLK * XQ_PITCH)        // +16512
#define OFF_LOSS (OFF_RR + T_BLK)
#define OFF_CCS  (OFF_LOSS + T_BLK)
#define OFF_ABF  (OFF_CCS + CHUNK)                  // 33408 (16B aligned)
#define ABF_F    (T_BLK * BF_PITCH / 2)             // 8704 floats
#define OFF_BBF  (OFF_ABF + ABF_F)
#define BBF_F    (CHUNK * BF_PITCH / 2)             // 8704 floats
#define SM_TOTAL_F (OFF_BBF + BBF_F)
#define SMEM_BYTES (SM_TOTAL_F * 4)                 // 203264 B

// Aliases inside BBF region (valid only after GEMM of a stage)
#define RED_ENT  24                                 // 2 cw-halves * 4 quad-lanes * top-3
#define NCAND    6

__device__ float          g_cc[NQ * KCB];
__device__ __nv_bfloat16  g_cbh[NQ * KCB * E_DIM];  // bf16 codebook (selection only)
__device__ float          g_partials[NBLOCKS];

// NEON-style vectorized sum-of-squares (XLA:CPU fast-math reduce) — VERIFIED bitwise vs ref.
__device__ __forceinline__ float neon_sumsq(const float* v, int stride) {
    float a0=0.f,a1=0.f,a2=0.f,a3=0.f,b0=0.f,b1=0.f,b2=0.f,b3=0.f;
    #pragma unroll 4
    for (int k = 0; k < E_DIM; k += 8) {
        float v0=v[(k+0)*stride], v1=v[(k+1)*stride], v2=v[(k+2)*stride], v3=v[(k+3)*stride];
        float v4=v[(k+4)*stride], v5=v[(k+5)*stride], v6=v[(k+6)*stride], v7=v[(k+7)*stride];
        a0=__fmaf_rn(v0,v0,a0); a1=__fmaf_rn(v1,v1,a1);
        a2=__fmaf_rn(v2,v2,a2); a3=__fmaf_rn(v3,v3,a3);
        b0=__fmaf_rn(v4,v4,b0); b1=__fmaf_rn(v5,v5,b1);
        b2=__fmaf_rn(v6,v6,b2); b3=__fmaf_rn(v7,v7,b3);
    }
    float s0=__fadd_rn(a0,b0), s1=__fadd_rn(a1,b1);
    float s2=__fadd_rn(a2,b2), s3=__fadd_rn(a3,b3);
    return __fadd_rn(__fadd_rn(s0,s1), __fadd_rn(s2,s3));
}

__global__ void prep_kernel(const float* __restrict__ cb) {
    int c = blockIdx.x * blockDim.x + threadIdx.x;
    if (c < NQ * KCB) {
        const float* row = cb + (size_t)c * E_DIM;
        g_cc[c] = neon_sumsq(row, 1);
        __nv_bfloat16* dst = g_cbh + (size_t)c * E_DIM;
        #pragma unroll 8
        for (int k = 0; k < E_DIM; ++k) dst[k] = __float2bfloat16(row[k]);
    }
}

__device__ __forceinline__ void ldsm_x4(uint32_t* r, uint32_t addr) {
    asm volatile("ldmatrix.sync.aligned.m8n8.x4.shared.b16 {%0,%1,%2,%3}, [%4];"
        : "=r"(r[0]), "=r"(r[1]), "=r"(r[2]), "=r"(r[3]) : "r"(addr));
}
__device__ __forceinline__ void mma_bf16(float* d, const uint32_t* a, const uint32_t* b) {
    asm volatile("mma.sync.aligned.m16n8k16.row.col.f32.bf16.bf16.f32 "
        "{%0,%1,%2,%3}, {%4,%5,%6,%7}, {%8,%9}, {%0,%1,%2,%3};"
        : "+f"(d[0]), "+f"(d[1]), "+f"(d[2]), "+f"(d[3])
        : "r"(a[0]), "r"(a[1]), "r"(a[2]), "r"(a[3]), "r"(b[0]), "r"(b[1]));
}
__device__ __forceinline__ void ins3(float v, int c, float* tv, int* ti) {
    if (v < tv[0]) { tv[2]=tv[1]; ti[2]=ti[1]; tv[1]=tv[0]; ti[1]=ti[0]; tv[0]=v; ti[0]=c; }
    else if (v < tv[1]) { tv[2]=tv[1]; ti[2]=ti[1]; tv[1]=v; ti[1]=c; }
    else if (v < tv[2]) { tv[2]=v; ti[2]=c; }
}

__global__ void __launch_bounds__(NTHREADS, 1)
rvq_kernel(const float* __restrict__ x, const float* __restrict__ cb, float* __restrict__ out)
{
    extern __shared__ float sm[];
    float* xs      = sm + OFF_XS;
    float* xq      = sm + OFF_XQ;
    float* rr      = sm + OFF_RR;
    float* lossbuf = sm + OFF_LOSS;
    float* ccs     = sm + OFF_CCS;
    __nv_bfloat16* abf = (__nv_bfloat16*)(sm + OFF_ABF);
    __nv_bfloat16* bbf = (__nv_bfloat16*)(sm + OFF_BBF);
    // Aliases in BBF region (post-GEMM phases only)
    float* red_d3 = sm + OFF_BBF;                    // [t][24]
    int*   red_i3 = (int*)(sm + OFF_BBF + 3072);     // [t][24]
    int*   cand   = (int*)(sm + OFF_BBF + 6144);     // [t][6]
    float* dem    = sm + OFF_BBF + 6912;             // [t][6]

    const int tid  = threadIdx.x;
    const int lane = tid & 31;
    const int wid  = tid >> 5;        // 0..15
    const int wt   = wid >> 1;        // token tile (8 tiles of 16)
    const int wc   = wid & 1;         // codeword half (2 halves of 64)
    const int t0   = blockIdx.x * T_BLK;

    const uint32_t abf_u = (uint32_t)__cvta_generic_to_shared(abf);
    const uint32_t bbf_u = (uint32_t)__cvta_generic_to_shared(bbf);
    // ldmatrix per-lane base addresses
    const uint32_t a_base = abf_u + (uint32_t)(wt * 16 + (lane & 15)) * (BF_PITCH * 2)
                                  + (uint32_t)((lane >> 4) << 4);
    const uint32_t b_base = bbf_u + (uint32_t)(wc * 64 + (lane & 7)) * (BF_PITCH * 2)
                                  + (uint32_t)((lane >> 3) << 4);

    // ---- Load x tile into xs (transposed), zero xq/lossbuf.
    {
        const float4* x4 = (const float4*)(x + (size_t)t0 * E_DIM);
        #pragma unroll
        for (int r = 0; r < (T_BLK * (E_DIM / 4)) / NTHREADS; ++r) {
            int f  = tid + NTHREADS * r;
            int t  = f >> 5;
            int k4 = f & 31;
            float4 v = x4[t * 32 + k4];
            xs[(k4 * 4 + 0) * XS_PITCH + t] = v.x;
            xs[(k4 * 4 + 1) * XS_PITCH + t] = v.y;
            xs[(k4 * 4 + 2) * XS_PITCH + t] = v.z;
            xs[(k4 * 4 + 3) * XS_PITCH + t] = v.w;
        }
        for (int o = tid; o < T_BLK * XQ_PITCH; o += NTHREADS) xq[o] = 0.0f;
        if (tid < T_BLK) lossbuf[tid] = 0.0f;
    }

    for (int s = 0; s <= NQ; ++s) {
        __syncthreads();
        // ---- rr (NEON emu, gold) + loss; convert residual to bf16 [t][k].
        if (tid < T_BLK) {
            float a = neon_sumsq(xs + tid, XS_PITCH);
            rr[tid] = a;
            if (s > 0) lossbuf[tid] += a;
        }
        if (s < NQ) {
            int t  = tid & 127;
            int ks = (tid >> 7) * 32;
            #pragma unroll 8
            for (int kk = 0; kk < 32; kk += 2) {
                int k = ks + kk;
                __nv_bfloat162 p = __floats2bfloat162_rn(xs[k * XS_PITCH + t],
                                                         xs[(k + 1) * XS_PITCH + t]);
                *(__nv_bfloat162*)(abf + t * BF_PITCH + k) = p;
            }
        }
        __syncthreads();
        if (s == NQ) break;

        // ---- per-lane running top-3, per token-row (2 rows per lane)
        float t3v[2][3]; int t3i[2][3];
        #pragma unroll
        for (int h = 0; h < 2; ++h)
            #pragma unroll
            for (int e = 0; e < 3; ++e) { t3v[h][e] = __int_as_float(0x7f800000); t3i[h][e] = 0x7fffffff; }

        for (int ch = 0; ch < NCHUNKS; ++ch) {
            // load bf16 codebook chunk + cc chunk
            {
                const uint4* src = (const uint4*)(g_cbh + ((size_t)s * KCB + ch * CHUNK) * E_DIM);
                #pragma unroll
                for (int r = 0; r < 4; ++r) {
                    int f = tid + NTHREADS * r;
                    int row = f >> 4, seg = f & 15;
                    *(uint4*)((char*)bbf + row * (BF_PITCH * 2) + seg * 16) = src[row * 16 + seg];
                }
                if (tid < CHUNK) ccs[tid] = g_cc[s * KCB + ch * CHUNK + tid];
            }
            __syncthreads();

            // ---- tensor-core GEMM: D[16 tok][64 cw] per warp, K=128
            float d[8][4];
            #pragma unroll
            for (int nt = 0; nt < 8; ++nt)
                #pragma unroll
                for (int i = 0; i < 4; ++i) d[nt][i] = 0.0f;

            #pragma unroll
            for (int kb = 0; kb < E_DIM; kb += 32) {
                uint32_t a0[4], a1[4];
                ldsm_x4(a0, a_base + kb * 2);
                ldsm_x4(a1, a_base + kb * 2 + 32);
                #pragma unroll
                for (int nt = 0; nt < 8; ++nt) {
                    uint32_t b[4];
                    ldsm_x4(b, b_base + nt * (8 * BF_PITCH * 2) + kb * 2);
                    mma_bf16(d[nt], a0, b);
                    mma_bf16(d[nt], a1, b + 2);
                }
            }

            // ---- selection epilogue: v = cc - 2*dot (rr cancels per token)
            const int clq = wc * 64 + (lane & 3) * 2;
            #pragma unroll
            for (int nt = 0; nt < 8; ++nt) {
                int cl = clq + nt * 8;
                float cc0 = ccs[cl], cc1 = ccs[cl + 1];
                int g0 = ch * CHUNK + cl;
                ins3(cc0 - 2.0f * d[nt][0], g0,     t3v[0], t3i[0]);
                ins3(cc1 - 2.0f * d[nt][1], g0 + 1, t3v[0], t3i[0]);
                ins3(cc0 - 2.0f * d[nt][2], g0,     t3v[1], t3i[1]);
                ins3(cc1 - 2.0f * d[nt][3], g0 + 1, t3v[1], t3i[1]);
            }
            __syncthreads();
        }

        // ---- dump per-lane top-3 (BBF now dead -> red buffers)
        {
            int tr0 = wt * 16 + (lane >> 2);
            int slot = wc * 12 + (lane & 3) * 3;
            #pragma unroll
            for (int e = 0; e < 3; ++e) {
                red_d3[tr0 * RED_ENT + slot + e]        = t3v[0][e];
                red_i3[tr0 * RED_ENT + slot + e]        = t3i[0][e];
                red_d3[(tr0 + 8) * RED_ENT + slot + e]  = t3v[1][e];
                red_i3[(tr0 + 8) * RED_ENT + slot + e]  = t3i[1][e];
            }
        }
        __syncthreads();

        // ---- phase A: per-token merge 24 -> top-6 candidates
        if (tid < T_BLK) {
            float tv[NCAND]; int ti[NCAND];
            #pragma unroll
            for (int q = 0; q < NCAND; ++q) { tv[q] = __int_as_float(0x7f800000); ti[q] = 0x7fffffff; }
            for (int g = 0; g < RED_ENT; ++g) {
                float v = red_d3[tid * RED_ENT + g];
                int   c = red_i3[tid * RED_ENT + g];
                #pragma unroll
                for (int q = 0; q < NCAND; ++q) {
                    bool better = (v < tv[q]) || (v == tv[q] && c < ti[q]);
                    if (better) { float vt = tv[q]; int ct = ti[q]; tv[q] = v; ti[q] = c; v = vt; c = ct; }
                }
            }
            #pragma unroll
            for (int q = 0; q < NCAND; ++q) cand[tid * NCAND + q] = ti[q];
        }
        __syncthreads();

        // ---- phase B: gold refinement dots (seq-FMA, Eigen-consistent), parallel over 512 thr
        {
            int t = tid & 127;
            int g = tid >> 7;                         // 0..3
            float rrt = rr[t];
            #pragma unroll
            for (int rep = 0; rep < 2; ++rep) {
                int q = g + rep * 4;
                if (q >= NCAND) break;
                int c = cand[t * NCAND + q];
                const float* crow = cb + (size_t)(s * KCB + c) * E_DIM;
                float hs = 0.0f;
                #pragma unroll 16
                for (int k = 0; k < E_DIM; ++k)
                    hs = __fmaf_rn(xs[k * XS_PITCH + t], crow[k], hs);
                dem[t * NCAND + q] = __fadd_rn(__fsub_rn(rrt, __fmul_rn(2.0f, hs)),
                                               g_cc[s * KCB + c]);
            }
        }
        __syncthreads();

        // ---- phase C: pick winner (gold comparator) + straight-through update
        if (tid < T_BLK) {
            float bestv = 0.0f; int besti = -1;
            #pragma unroll
            for (int q = 0; q < NCAND; ++q) {
                int   c = cand[tid * NCAND + q];
                float v = dem[tid * NCAND + q];
                if (besti < 0 || v < bestv || (v == bestv && c < besti)) { bestv = v; besti = c; }
            }
            out[OUT_IDX_OFF + (size_t)(t0 + tid) * NQ + s] = (float)besti;

            const float4* qrow = (const float4*)(cb + (size_t)(s * KCB + besti) * E_DIM);
            #pragma unroll 4
            for (int k4 = 0; k4 < 32; ++k4) {
                float4 q4 = qrow[k4];
                #pragma unroll
                for (int m = 0; m < 4; ++m) {
                    int   k  = k4 * 4 + m;
                    float qv = (m == 0) ? q4.x : (m == 1) ? q4.y : (m == 2) ? q4.z : q4.w;
                    float r  = xs[k * XS_PITCH + tid];
                    float qt = __fadd_rn(r, __fsub_rn(qv, r));
                    xq[tid * XQ_PITCH + k] = __fadd_rn(xq[tid * XQ_PITCH + k], qt);
                    xs[k * XS_PITCH + tid] = __fsub_rn(r, qt);
                }
            }
        }
    }

    if (tid == 0) {
        float a = 0.0f;
        for (int t = 0; t < T_BLK; ++t) a += lossbuf[t];
        g_partials[blockIdx.x] = a;
    }

    {
        float* o = out + (size_t)t0 * E_DIM;
        for (int f = tid; f < T_BLK * E_DIM; f += NTHREADS)
            o[f] = xq[(f >> 7) * XQ_PITCH + (f & 127)];
    }
}

__global__ void finalize_kernel(float* __restrict__ out) {
    if (threadIdx.x == 0 && blockIdx.x == 0) {
        double a = 0.0;
        for (int i = 0; i < NBLOCKS; ++i) a += (double)g_partials[i];
        out[OUT_LOSS_OFF] = (float)(a * (0.25 / (4.0 * (double)N_TOKENS * (double)E_DIM)));
    }
}

extern "C" void kernel_launch(void* const* d_in, const int* in_sizes, int n_in,
                              void* d_out, int out_size) {
    (void)in_sizes; (void)n_in; (void)out_size;
    const float* x  = (const float*)d_in[0];
    const float* cb = (const float*)d_in[1];
    float* out = (float*)d_out;

    cudaFuncSetAttribute(rvq_kernel, cudaFuncAttributeMaxDynamicSharedMemorySize, SMEM_BYTES);

    prep_kernel<<<(NQ * KCB + 255) / 256, 256>>>(cb);
    rvq_kernel<<<NBLOCKS, NTHREADS, SMEM_BYTES>>>(x, cb, out);
    finalize_kernel<<<1, 1>>>(out);
}